// round 5
// baseline (speedup 1.0000x reference)
#include <cuda_runtime.h>

#define SLEN 4096
#define NBATCH 8
#define TOK (NBATCH*SLEN)
#define EMB 1024
#define HD 64
#define HALF 32

// Scratch for projected q/k/v (device globals: allocation-free rule)
__device__ float g_K[TOK*HD];
__device__ float g_Q[TOK*HD];
__device__ float g_V[TOK*HD];

// ---------- packed f32x2 helpers (Blackwell-only, PTX required) ----------
__device__ __forceinline__ unsigned long long pk2(float lo, float hi) {
    unsigned long long r;
    asm("mov.b64 %0, {%1, %2};" : "=l"(r) : "f"(lo), "f"(hi));
    return r;
}
__device__ __forceinline__ void upk2(unsigned long long v, float& lo, float& hi) {
    asm("mov.b64 {%0, %1}, %2;" : "=f"(lo), "=f"(hi) : "l"(v));
}
__device__ __forceinline__ unsigned long long fma2(unsigned long long a, unsigned long long b, unsigned long long c) {
    unsigned long long d;
    asm("fma.rn.f32x2 %0, %1, %2, %3;" : "=l"(d) : "l"(a), "l"(b), "l"(c));
    return d;
}
__device__ __forceinline__ unsigned long long mul2(unsigned long long a, unsigned long long b) {
    unsigned long long d;
    asm("mul.rn.f32x2 %0, %1, %2;" : "=l"(d) : "l"(a), "l"(b));
    return d;
}

// =========================================================================
// Projection kernel v2: phase-1 packs f32x2 over the reduction dim k.
//   X tile [64][36] row-major (natural k-pairs); W1 staged TRANSPOSED
//   [96 cols][36] so its k-pairs are natural too -> zero broadcast MOVs.
//   Thread (ty,tx): 4 tokens x 6 cols (cols interleaved: tx+16*jc).
//   Phase-2 (tiny fraction of work) unchanged.
// =========================================================================
__global__ __launch_bounds__(256) void proj_kernel(
    const float* __restrict__ x,
    const float* __restrict__ wk1, const float* __restrict__ bk1, const float* __restrict__ wk2,
    const float* __restrict__ wq1, const float* __restrict__ bq1, const float* __restrict__ wq2,
    const float* __restrict__ wv1, const float* __restrict__ bv1, const float* __restrict__ wv2)
{
    __shared__ __align__(16) float smem[12288];   // 48 KB
    float* Xs  = smem;          // [64][36] = 2304 floats   (phase 1)
    float* W1t = smem + 2304;   // [96][36] = 3456 floats   (phase 1, ends 5760)
    float* Hs  = smem;          // [64][96] = 6144 floats   (phase 2, unions)
    float* W2s = smem + 6144;   // [3][32][64] = 6144 floats

    const int tid  = threadIdx.x;
    const int tok0 = blockIdx.x * 64;

    // W2 staged once; region [6144,12288) untouched by phase 1.
    {
        for (int idx = tid; idx < 3*32*64; idx += 256) {
            int p = idx >> 11, rem = idx & 2047;
            const float* w2 = (p == 0) ? wk2 : ((p == 1) ? wq2 : wv2);
            W2s[idx] = w2[rem];
        }
    }

    const int tx = tid & 15;
    const int ty = tid >> 4;
    const int ty4 = ty * 4;

    unsigned long long acc2[4][6];
#pragma unroll
    for (int i = 0; i < 4; i++)
#pragma unroll
        for (int j = 0; j < 6; j++) acc2[i][j] = 0ull;

    for (int k0 = 0; k0 < EMB; k0 += 32) {
        __syncthreads();
        // stage X tile [64 tokens][32 k], pitch 36 (float4 stores)
        for (int idx = tid; idx < 512; idx += 256) {
            int t = idx >> 3, kf = idx & 7;
            *(float4*)&Xs[t*36 + 4*kf] =
                ((const float4*)x)[(long long)(tok0 + t)*(EMB/4) + (k0 >> 2) + kf];
        }
        // stage W1 transposed: W1t[col][kk], col = p*32+h
        for (int idx = tid; idx < 3072; idx += 256) {
            int p = idx >> 10, rem = idx & 1023;
            int kk = rem >> 5, h = rem & 31;
            const float* w1 = (p == 0) ? wk1 : ((p == 1) ? wq1 : wv1);
            W1t[(p*32 + h)*36 + kk] = w1[(k0 + kk)*HALF + h];
        }
        __syncthreads();

#pragma unroll
        for (int c = 0; c < 8; c++) {          // 16B chunks (4 k's)
            ulonglong2 xv[4];
#pragma unroll
            for (int i = 0; i < 4; i++)
                xv[i] = *(const ulonglong2*)&Xs[(ty4 + i)*36 + 4*c];
#pragma unroll
            for (int jc = 0; jc < 6; jc++) {
                ulonglong2 wv = *(const ulonglong2*)&W1t[(tx + 16*jc)*36 + 4*c];
#pragma unroll
                for (int i = 0; i < 4; i++) {
                    acc2[i][jc] = fma2(xv[i].x, wv.x, acc2[i][jc]);
                    acc2[i][jc] = fma2(xv[i].y, wv.y, acc2[i][jc]);
                }
            }
        }
    }
    __syncthreads();

    // horizontal add + bias + tanh -> Hs (col = tx + 16*jc)
#pragma unroll
    for (int jc = 0; jc < 6; jc++) {
        int p = jc >> 1;                       // uniform per jc
        int h = tx + 16*(jc & 1);
        const float* b1 = (p == 0) ? bk1 : ((p == 1) ? bq1 : bv1);
        float bb = b1[h];
#pragma unroll
        for (int i = 0; i < 4; i++) {
            float lo, hi;
            upk2(acc2[i][jc], lo, hi);
            Hs[(ty4 + i)*96 + 16*jc + tx] = tanhf(lo + hi + bb);
        }
    }
    __syncthreads();

    // Phase 2: out[t, p, h] = sum_j Hs[t, p*32+j] * W2s[p][j][h]
    for (int idx = tid; idx < 64*96; idx += 256) {
        int t = idx / 96, cp = idx % 96;
        int p = cp >> 5, hp = cp & 31;
        unsigned long long acc = 0ull;
#pragma unroll
        for (int j = 0; j < 32; j++) {
            float a = Hs[t*96 + p*32 + j];
            unsigned long long b = *(const unsigned long long*)&W2s[p*2048 + j*64 + 2*hp];
            acc = fma2(pk2(a, a), b, acc);
        }
        float lo, hi;
        upk2(acc, lo, hi);
        float* gout = (p == 0) ? g_K : ((p == 1) ? g_Q : g_V);
        long long o = (long long)(tok0 + t)*HD + 2*hp;
        gout[o]     = lo;
        gout[o + 1] = hi;
    }
}

// =========================================================================
// Causal flash attention v4: reduction-packed f32x2 (zero broadcast MOVs).
//   Block = 64 queries, 256 threads = (tq 0..15) x (tk 0..15).
//   QK packs over d: Q,K row-major tiles; thread -> S[4q][4k],
//     keys interleaved {tk+16j}. 8 LDS.128 + 32 fma2 per 16B d-chunk.
//   PV packs over k: P row-major [q][k] (natural), V transposed [d][k];
//     thread -> O[4q][4d], dims interleaved {tk+16jj}.
//   All tiles pitch-64 + XOR 16B-group swizzle (grp ^= row&15):
//     interleaved-row LDS.128 reads hit the 2-wavefront floor.
//   P aliases K. Smem = 3 x 16KB = 48KB exactly.
// =========================================================================
__global__ __launch_bounds__(256, 2) void attn_kernel(float* __restrict__ out)
{
    __shared__ __align__(16) float Qs[4096];   // [q][d], prescaled, no swizzle (broadcast reads)
    __shared__ __align__(16) float KP[4096];   // K [k-row][d] swizzled; later P [q][k] swizzled
    __shared__ __align__(16) float Vt[4096];   // V^T [d][k] swizzled

    const int tid = threadIdx.x;
    const int tq  = tid >> 4;
    const int tk  = tid & 15;
    const int tq4 = tq * 4;
    const int bid = blockIdx.x;
    const int b   = bid & 7;
    const int qt  = 63 - (bid >> 3);           // heavy diagonal blocks first
    const long long tokbase = (long long)b * SLEN;
    const long long qbase   = (tokbase + (long long)qt*64) * HD;

    // ---- stage Q (row-major, prescaled); visible after first tile's sync ----
    {
        const float4* gq = (const float4*)(g_Q + qbase);
#pragma unroll
        for (int it = 0; it < 4; it++) {
            int idx = tid + it*256;
            int r = idx >> 4, f = idx & 15;
            float4 v = gq[idx];
            v.x *= 0.125f; v.y *= 0.125f; v.z *= 0.125f; v.w *= 0.125f;
            *(float4*)&Qs[r*64 + 4*f] = v;
        }
    }

    float m[4], l[4];
    unsigned long long o2[4][4];               // [q][d-group], packed over k-pairs
#pragma unroll
    for (int i = 0; i < 4; i++) {
        m[i] = -1e30f; l[i] = 0.f;
#pragma unroll
        for (int j = 0; j < 4; j++) o2[i][j] = 0ull;
    }

    for (int kt = 0; kt <= qt; kt++) {
        __syncthreads();   // A: prior tile's P/Vt reads complete
        {
            const long long base = (tokbase + (long long)kt*64) * HD;
            const float4* gk = (const float4*)(g_K + base);
            const float4* gv = (const float4*)(g_V + base);
            // K: row-major, group-swizzled
#pragma unroll
            for (int it = 0; it < 4; it++) {
                int idx = tid + it*256;
                int r = idx >> 4, f = idx & 15;
                *(float4*)&KP[r*64 + ((f ^ (r & 15)) << 2)] = gk[idx];
            }
            // V^T: thread covers d-group fv, tokens rbase+16*it
            int fv = tid >> 4;
            int rb = tid & 15;
#pragma unroll
            for (int it = 0; it < 4; it++) {
                int r = rb + 16*it;
                float4 v = gv[r*16 + fv];
                int d0 = 4*fv;
                int rg = r >> 2, rl = r & 3;
                Vt[(d0+0)*64 + ((rg ^ ((d0+0) & 15)) << 2) + rl] = v.x;
                Vt[(d0+1)*64 + ((rg ^ ((d0+1) & 15)) << 2) + rl] = v.y;
                Vt[(d0+2)*64 + ((rg ^ ((d0+2) & 15)) << 2) + rl] = v.z;
                Vt[(d0+3)*64 + ((rg ^ ((d0+3) & 15)) << 2) + rl] = v.w;
            }
        }
        __syncthreads();   // B: tiles staged

        // ---- QK: S[4q][4k], packed over d-pairs ----
        unsigned long long s2[4][4];
#pragma unroll
        for (int i = 0; i < 4; i++)
#pragma unroll
            for (int j = 0; j < 4; j++) s2[i][j] = 0ull;

#pragma unroll
        for (int c = 0; c < 16; c++) {         // 16B d-chunks
            ulonglong2 qv[4];
#pragma unroll
            for (int i = 0; i < 4; i++)
                qv[i] = *(const ulonglong2*)&Qs[(tq4 + i)*64 + 4*c];
            int kswz = ((c ^ tk) << 2);
#pragma unroll
            for (int j = 0; j < 4; j++) {
                ulonglong2 kv = *(const ulonglong2*)&KP[(tk + 16*j)*64 + kswz];
#pragma unroll
                for (int i = 0; i < 4; i++) {
                    s2[i][j] = fma2(qv[i].x, kv.x, s2[i][j]);
                    s2[i][j] = fma2(qv[i].y, kv.y, s2[i][j]);
                }
            }
        }

        float s[4][4];
#pragma unroll
        for (int i = 0; i < 4; i++)
#pragma unroll
            for (int j = 0; j < 4; j++) {
                float lo, hi; upk2(s2[i][j], lo, hi); s[i][j] = lo + hi;
            }

        if (kt == qt) {    // diagonal tile mask (uniform branch)
#pragma unroll
            for (int i = 0; i < 4; i++)
#pragma unroll
                for (int j = 0; j < 4; j++)
                    if (tk + 16*j > tq4 + i) s[i][j] = -1e30f;
        }

        // ---- online softmax; row stats over the 16 tk lanes ----
#pragma unroll
        for (int i = 0; i < 4; i++) {
            float mn = fmaxf(fmaxf(s[i][0], s[i][1]), fmaxf(s[i][2], s[i][3]));
            mn = fmaxf(mn, m[i]);
            mn = fmaxf(mn, __shfl_xor_sync(0xffffffffu, mn, 1));
            mn = fmaxf(mn, __shfl_xor_sync(0xffffffffu, mn, 2));
            mn = fmaxf(mn, __shfl_xor_sync(0xffffffffu, mn, 4));
            mn = fmaxf(mn, __shfl_xor_sync(0xffffffffu, mn, 8));
            float c = __expf(m[i] - mn);
            m[i] = mn;
            float p0 = __expf(s[i][0] - mn);
            float p1 = __expf(s[i][1] - mn);
            float p2 = __expf(s[i][2] - mn);
            float p3 = __expf(s[i][3] - mn);
            l[i] = l[i]*c + (p0 + p1) + (p2 + p3);
            unsigned long long cc = pk2(c, c);
#pragma unroll
            for (int j = 0; j < 4; j++) o2[i][j] = mul2(o2[i][j], cc);
            s[i][0] = p0; s[i][1] = p1; s[i][2] = p2; s[i][3] = p3;
        }

        __syncthreads();   // C: all warps done reading K -> overwrite with P
#pragma unroll
        for (int i = 0; i < 4; i++) {
            int row = tq4 + i;
            int rx = row & 15;
#pragma unroll
            for (int j = 0; j < 4; j++) {
                int col = tk + 16*j;
                KP[row*64 + (((col >> 2) ^ rx) << 2) + (col & 3)] = s[i][j];
            }
        }
        __syncwarp();      // P rows read by the same warp that wrote them

        // ---- PV: O[4q][4d-groups], packed over k-pairs ----
#pragma unroll
        for (int c = 0; c < 16; c++) {         // 16B k-chunks
            ulonglong2 pv[4];
#pragma unroll
            for (int i = 0; i < 4; i++) {
                int row = tq4 + i;
                pv[i] = *(const ulonglong2*)&KP[row*64 + ((c ^ (row & 15)) << 2)];
            }
            int vswz = ((c ^ tk) << 2);
#pragma unroll
            for (int jj = 0; jj < 4; jj++) {
                ulonglong2 vv = *(const ulonglong2*)&Vt[(tk + 16*jj)*64 + vswz];
#pragma unroll
                for (int i = 0; i < 4; i++) {
                    o2[i][jj] = fma2(pv[i].x, vv.x, o2[i][jj]);
                    o2[i][jj] = fma2(pv[i].y, vv.y, o2[i][jj]);
                }
            }
        }
    }

    // ---- merge l over tk lanes; horizontal-add o2; write O ----
#pragma unroll
    for (int i = 0; i < 4; i++) {
        float lt = l[i];
        lt += __shfl_xor_sync(0xffffffffu, lt, 1);
        lt += __shfl_xor_sync(0xffffffffu, lt, 2);
        lt += __shfl_xor_sync(0xffffffffu, lt, 4);
        lt += __shfl_xor_sync(0xffffffffu, lt, 8);
        float inv = 1.0f / lt;
        float* orow = out + qbase + (long long)(tq4 + i)*HD + tk;
#pragma unroll
        for (int jj = 0; jj < 4; jj++) {
            float lo, hi;
            upk2(o2[i][jj], lo, hi);
            orow[16*jj] = (lo + hi) * inv;
        }
    }
}

extern "C" void kernel_launch(void* const* d_in, const int* in_sizes, int n_in,
                              void* d_out, int out_size)
{
    const float* x   = (const float*)d_in[0];
    const float* wk1 = (const float*)d_in[1];
    const float* bk1 = (const float*)d_in[2];
    const float* wk2 = (const float*)d_in[3];
    const float* wq1 = (const float*)d_in[4];
    const float* bq1 = (const float*)d_in[5];
    const float* wq2 = (const float*)d_in[6];
    const float* wv1 = (const float*)d_in[7];
    const float* bv1 = (const float*)d_in[8];
    const float* wv2 = (const float*)d_in[9];

    proj_kernel<<<TOK/64, 256>>>(x, wk1, bk1, wk2, wq1, bq1, wq2, wv1, bv1, wv2);
    attn_kernel<<<NBATCH * (SLEN/64), 256>>>((float*)d_out);
}

// round 8
// speedup vs baseline: 1.4678x; 1.4678x over previous
#include <cuda_runtime.h>

#define SLEN 4096
#define NBATCH 8
#define TOK (NBATCH*SLEN)
#define EMB 1024
#define HD 64
#define HALF 32

// Scratch for projected q/k/v (device globals: allocation-free rule)
__device__ float g_K[TOK*HD];
__device__ float g_Q[TOK*HD];
__device__ float g_V[TOK*HD];

// ---------- packed f32x2 helpers (proj kernel) ----------
__device__ __forceinline__ unsigned long long pk2(float lo, float hi) {
    unsigned long long r;
    asm("mov.b64 %0, {%1, %2};" : "=l"(r) : "f"(lo), "f"(hi));
    return r;
}
__device__ __forceinline__ void upk2(unsigned long long v, float& lo, float& hi) {
    asm("mov.b64 {%0, %1}, %2;" : "=f"(lo), "=f"(hi) : "l"(v));
}
__device__ __forceinline__ unsigned long long fma2(unsigned long long a, unsigned long long b, unsigned long long c) {
    unsigned long long d;
    asm("fma.rn.f32x2 %0, %1, %2, %3;" : "=l"(d) : "l"(a), "l"(b), "l"(c));
    return d;
}

// ---------- mma.sync helpers (sm_80+ PTX; works on base sm_100) ----------
__device__ __forceinline__ unsigned to_tf32(float f) {
    unsigned u;
    asm("cvt.rna.tf32.f32 %0, %1;" : "=r"(u) : "f"(f));
    return u;
}
__device__ __forceinline__ float ex2f(float x) {
    float r;
    asm("ex2.approx.f32 %0, %1;" : "=f"(r) : "f"(x));
    return r;
}
// D(16x8) += A(16x8) * B(8x8), tf32
__device__ __forceinline__ void mma8(float* c, const unsigned* a, unsigned b0, unsigned b1) {
    asm("mma.sync.aligned.m16n8k8.row.col.f32.tf32.tf32.f32 "
        "{%0,%1,%2,%3}, {%4,%5,%6,%7}, {%8,%9}, {%0,%1,%2,%3};"
        : "+f"(c[0]), "+f"(c[1]), "+f"(c[2]), "+f"(c[3])
        : "r"(a[0]), "r"(a[1]), "r"(a[2]), "r"(a[3]), "r"(b0), "r"(b1));
}

// =========================================================================
// Projection kernel (R3 version — known good, 261us)
// =========================================================================
__global__ __launch_bounds__(256) void proj_kernel(
    const float* __restrict__ x,
    const float* __restrict__ wk1, const float* __restrict__ bk1, const float* __restrict__ wk2,
    const float* __restrict__ wq1, const float* __restrict__ bq1, const float* __restrict__ wq2,
    const float* __restrict__ wv1, const float* __restrict__ bv1, const float* __restrict__ wv2)
{
    __shared__ __align__(16) float smem[12288];
    float* Xs  = smem;
    float* Ws  = smem + 2112;
    float* Hs  = smem;
    float* W2s = smem + 6144;

    const int tid  = threadIdx.x;
    const int tok0 = blockIdx.x * 64;

    {
        for (int idx = tid; idx < 3*32*64; idx += 256) {
            int p = idx >> 11, rem = idx & 2047;
            const float* w2 = (p == 0) ? wk2 : ((p == 1) ? wq2 : wv2);
            W2s[idx] = w2[rem];
        }
    }

    const int tx = tid & 15;
    const int ty = tid >> 4;

    unsigned long long acc2[4][3];
#pragma unroll
    for (int i = 0; i < 4; i++)
#pragma unroll
        for (int j = 0; j < 3; j++) acc2[i][j] = 0ull;

    for (int k0 = 0; k0 < EMB; k0 += 32) {
        __syncthreads();
        for (int idx = tid; idx < 64*32; idx += 256) {
            int t = idx >> 5, kk = idx & 31;
            Xs[t*33 + kk] = x[(long long)(tok0 + t)*EMB + k0 + kk];
        }
        for (int idx = tid; idx < 32*96; idx += 256) {
            int kk = idx / 96, c = idx % 96;
            int p = c >> 5, h = c & 31;
            const float* w1 = (p == 0) ? wk1 : ((p == 1) ? wq1 : wv1);
            Ws[kk*96 + c] = w1[(k0 + kk)*HALF + h];
        }
        __syncthreads();

#pragma unroll
        for (int kk = 0; kk < 32; kk++) {
            unsigned long long a2[4];
#pragma unroll
            for (int i = 0; i < 4; i++) {
                float a = Xs[(ty*4 + i)*33 + kk];
                a2[i] = pk2(a, a);
            }
            unsigned long long b2[3];
#pragma unroll
            for (int j = 0; j < 3; j++)
                b2[j] = *(const unsigned long long*)&Ws[kk*96 + tx*6 + 2*j];
#pragma unroll
            for (int i = 0; i < 4; i++)
#pragma unroll
                for (int j = 0; j < 3; j++)
                    acc2[i][j] = fma2(a2[i], b2[j], acc2[i][j]);
        }
    }
    __syncthreads();

#pragma unroll
    for (int i = 0; i < 4; i++) {
#pragma unroll
        for (int j = 0; j < 3; j++) {
            float lo, hi;
            upk2(acc2[i][j], lo, hi);
            int c0 = tx*6 + 2*j;
            int p0 = c0 >> 5, h0 = c0 & 31;
            const float* b1 = (p0 == 0) ? bk1 : ((p0 == 1) ? bq1 : bv1);
            lo = tanhf(lo + b1[h0]);
            hi = tanhf(hi + b1[h0 + 1]);
            Hs[(ty*4 + i)*96 + c0]     = lo;
            Hs[(ty*4 + i)*96 + c0 + 1] = hi;
        }
    }
    __syncthreads();

    for (int idx = tid; idx < 64*96; idx += 256) {
        int t = idx / 96, cp = idx % 96;
        int p = cp >> 5, hp = cp & 31;
        unsigned long long acc = 0ull;
#pragma unroll
        for (int j = 0; j < 32; j++) {
            float a = Hs[t*96 + p*32 + j];
            unsigned long long b = *(const unsigned long long*)&W2s[p*2048 + j*64 + 2*hp];
            acc = fma2(pk2(a, a), b, acc);
        }
        float lo, hi;
        upk2(acc, lo, hi);
        float* gout = (p == 0) ? g_K : ((p == 1) ? g_Q : g_V);
        long long o = (long long)(tok0 + t)*HD + 2*hp;
        gout[o]     = lo;
        gout[o + 1] = hi;
    }
}

// =========================================================================
// mma.sync tf32 flash attention (sm_100 base target; no tcgen05).
//   CTA = 64 queries, 128 threads = 4 warps x 16 query rows. 3 CTAs/SM.
//   Per 64-key tile:
//     QK: 3xTF32 (hi/lo split) m16n8k8 -> S[16x64] in C-fragments
//     softmax: p = 2^s (log2e folded into Q prescale; no-max, clamp 80)
//     P -> per-warp smem (pitch 68) -> PV: single tf32 mma, O accum in regs.
//   Pitches chosen for conflict-free fragment LDS: K 68, V 76, P 68.
//   l accumulated per-row in regs, reduced over lane%4 at the end.
// =========================================================================
#define PK 68
#define PV 76
#define SM_KHI 0
#define SM_KLO 4352
#define SM_V   8704
#define SM_P   13568
#define SM_FLOATS (13568 + 4*16*68)     // 17920 floats = 71680 B

__global__ __launch_bounds__(128, 3) void attn_mma(float* __restrict__ out)
{
    extern __shared__ float sm[];
    float* Khi = sm + SM_KHI;
    float* Klo = sm + SM_KLO;
    float* Vs  = sm + SM_V;

    const int tid = threadIdx.x;
    const int w   = tid >> 5;
    const int lane = tid & 31;
    const int g   = lane >> 2;       // row group 0..7
    const int r   = lane & 3;        // col-in-group 0..3
    float* Pw = sm + SM_P + w*(16*PK);

    const int bid = blockIdx.x;
    const int b   = bid & 7;
    const int qt  = 63 - (bid >> 3);        // heavy q-tiles first
    const int nk  = qt + 1;
    const long long qrow0 = (long long)b*SLEN + (long long)qt*64;
    const int q0 = qt*64 + 16*w + g;        // this thread's two query rows
    const int q1 = q0 + 8;

    // ---- Q fragments (hi+lo), prescaled by 0.125*log2(e); held all kernel ----
    const float SC = 0.1803368801111204f;   // 1/sqrt(64) * log2(e)
    unsigned ahi[8][4], alo[8][4];
    {
        const float* qA = g_Q + (qrow0 + 16*w + g)*HD + r;
        const float* qB = qA + 8*HD;
#pragma unroll
        for (int c = 0; c < 8; c++) {
#pragma unroll
            for (int u = 0; u < 4; u++) {
                const float* src = (u & 1) ? qB : qA;
                int d = 8*c + ((u & 2) ? 4 : 0);
                float v = src[d] * SC;
                unsigned h = to_tf32(v);
                ahi[c][u] = h;
                alo[c][u] = __float_as_uint(v - __uint_as_float(h));
            }
        }
    }

    float o[8][4];
#pragma unroll
    for (int j = 0; j < 8; j++)
#pragma unroll
        for (int u = 0; u < 4; u++) o[j][u] = 0.f;
    float l0 = 0.f, l1 = 0.f;

    for (int kt = 0; kt < nk; kt++) {
        __syncthreads();   // prior tile's K/V reads complete
        // ---- stage K (hi/lo split) and V ----
        {
            const long long kbase = ((long long)b*SLEN + (long long)kt*64) * HD;
            const float4* gk = (const float4*)(g_K + kbase);
            const float4* gv = (const float4*)(g_V + kbase);
#pragma unroll
            for (int it = 0; it < 8; it++) {
                int idx = tid + it*128;          // 1024 float4 slots
                int key = idx >> 4, f = idx & 15;
                float4 kk = gk[idx];
                float4 vv = gv[idx];
                int d0 = 4*f;
#pragma unroll
                for (int u = 0; u < 4; u++) {
                    float kv = (u == 0) ? kk.x : ((u == 1) ? kk.y : ((u == 2) ? kk.z : kk.w));
                    unsigned h = to_tf32(kv);
                    Khi[key*PK + d0 + u] = __uint_as_float(h);
                    Klo[key*PK + d0 + u] = kv - __uint_as_float(h);
                    float vvv = (u == 0) ? vv.x : ((u == 1) ? vv.y : ((u == 2) ? vv.z : vv.w));
                    Vs[key*PV + d0 + u] = vvv;
                }
            }
        }
        __syncthreads();

        // ---- QK: S[16 x 64] via 3xTF32 ----
        float s[8][4];
#pragma unroll
        for (int j = 0; j < 8; j++)
#pragma unroll
            for (int u = 0; u < 4; u++) s[j][u] = 0.f;

#pragma unroll
        for (int c = 0; c < 8; c++) {
#pragma unroll
            for (int j = 0; j < 8; j++) {
                // B frag: b0 = K[key=8j+g][d=8c+r], b1 = d+4
                int base = (8*j + g)*PK + 8*c + r;
                unsigned bh0 = __float_as_uint(Khi[base]);
                unsigned bh1 = __float_as_uint(Khi[base + 4]);
                unsigned bl0 = __float_as_uint(Klo[base]);
                unsigned bl1 = __float_as_uint(Klo[base + 4]);
                mma8(s[j], ahi[c], bh0, bh1);
                mma8(s[j], ahi[c], bl0, bl1);
                mma8(s[j], alo[c], bh0, bh1);
            }
        }

        // ---- softmax (p = 2^s, no-max) + causal mask + P to smem ----
        const int kb = kt*64;
        if (kt == qt) {       // diagonal tile masks (uniform branch)
#pragma unroll
            for (int j = 0; j < 8; j++) {
                int k0 = kb + 8*j + 2*r;
                float p0 = (k0     > q0) ? 0.f : ex2f(fminf(s[j][0], 80.f));
                float p1 = (k0 + 1 > q0) ? 0.f : ex2f(fminf(s[j][1], 80.f));
                float p2 = (k0     > q1) ? 0.f : ex2f(fminf(s[j][2], 80.f));
                float p3 = (k0 + 1 > q1) ? 0.f : ex2f(fminf(s[j][3], 80.f));
                l0 += p0 + p1; l1 += p2 + p3;
                Pw[g*PK + 8*j + 2*r]       = p0;
                Pw[g*PK + 8*j + 2*r + 1]   = p1;
                Pw[(g+8)*PK + 8*j + 2*r]   = p2;
                Pw[(g+8)*PK + 8*j + 2*r+1] = p3;
            }
        } else {
#pragma unroll
            for (int j = 0; j < 8; j++) {
                float p0 = ex2f(fminf(s[j][0], 80.f));
                float p1 = ex2f(fminf(s[j][1], 80.f));
                float p2 = ex2f(fminf(s[j][2], 80.f));
                float p3 = ex2f(fminf(s[j][3], 80.f));
                l0 += p0 + p1; l1 += p2 + p3;
                Pw[g*PK + 8*j + 2*r]       = p0;
                Pw[g*PK + 8*j + 2*r + 1]   = p1;
                Pw[(g+8)*PK + 8*j + 2*r]   = p2;
                Pw[(g+8)*PK + 8*j + 2*r+1] = p3;
            }
        }
        __syncwarp();      // P region is per-warp private

        // ---- PV: O[16 x 64] += P[16 x 64keys] * V[64keys x 64] ----
#pragma unroll
        for (int c = 0; c < 8; c++) {       // key chunks of 8
            unsigned ap[4];
            ap[0] = __float_as_uint(Pw[g*PK     + 8*c + r]);
            ap[1] = __float_as_uint(Pw[(g+8)*PK + 8*c + r]);
            ap[2] = __float_as_uint(Pw[g*PK     + 8*c + r + 4]);
            ap[3] = __float_as_uint(Pw[(g+8)*PK + 8*c + r + 4]);
#pragma unroll
            for (int j = 0; j < 8; j++) {
                unsigned b0 = __float_as_uint(Vs[(8*c + r)*PV     + 8*j + g]);
                unsigned b1 = __float_as_uint(Vs[(8*c + r + 4)*PV + 8*j + g]);
                mma8(o[j], ap, b0, b1);
            }
        }
    }

    // ---- reduce l over the 4 lanes of each row; normalize; store ----
    l0 += __shfl_xor_sync(0xffffffffu, l0, 1);
    l0 += __shfl_xor_sync(0xffffffffu, l0, 2);
    l1 += __shfl_xor_sync(0xffffffffu, l1, 1);
    l1 += __shfl_xor_sync(0xffffffffu, l1, 2);
    float inv0 = 1.0f / l0;
    float inv1 = 1.0f / l1;
    float* out0 = out + ((long long)b*SLEN + q0)*HD + 2*r;
    float* out1 = out + ((long long)b*SLEN + q1)*HD + 2*r;
#pragma unroll
    for (int j = 0; j < 8; j++) {
        *(float2*)(out0 + 8*j) = make_float2(o[j][0]*inv0, o[j][1]*inv0);
        *(float2*)(out1 + 8*j) = make_float2(o[j][2]*inv1, o[j][3]*inv1);
    }
}

extern "C" void kernel_launch(void* const* d_in, const int* in_sizes, int n_in,
                              void* d_out, int out_size)
{
    const float* x   = (const float*)d_in[0];
    const float* wk1 = (const float*)d_in[1];
    const float* bk1 = (const float*)d_in[2];
    const float* wk2 = (const float*)d_in[3];
    const float* wq1 = (const float*)d_in[4];
    const float* bq1 = (const float*)d_in[5];
    const float* wq2 = (const float*)d_in[6];
    const float* wv1 = (const float*)d_in[7];
    const float* bv1 = (const float*)d_in[8];
    const float* wv2 = (const float*)d_in[9];

    cudaFuncSetAttribute(attn_mma, cudaFuncAttributeMaxDynamicSharedMemorySize,
                         SM_FLOATS * 4);

    proj_kernel<<<TOK/64, 256>>>(x, wk1, bk1, wk2, wq1, bq1, wq2, wv1, bv1, wv2);
    attn_mma<<<NBATCH * (SLEN/64), 128, SM_FLOATS * 4>>>((float*)d_out);
}

// round 9
// speedup vs baseline: 1.9696x; 1.3418x over previous
#include <cuda_runtime.h>

#define SLEN 4096
#define NBATCH 8
#define TOK (NBATCH*SLEN)
#define EMB 1024
#define HD 64
#define HALF 32

// Scratch for projected q/k/v (device globals: allocation-free rule)
__device__ float g_K[TOK*HD];
__device__ float g_Q[TOK*HD];
__device__ float g_V[TOK*HD];

// ---------- packed f32x2 helpers (proj kernel) ----------
__device__ __forceinline__ unsigned long long pk2(float lo, float hi) {
    unsigned long long r;
    asm("mov.b64 %0, {%1, %2};" : "=l"(r) : "f"(lo), "f"(hi));
    return r;
}
__device__ __forceinline__ void upk2(unsigned long long v, float& lo, float& hi) {
    asm("mov.b64 {%0, %1}, %2;" : "=f"(lo), "=f"(hi) : "l"(v));
}
__device__ __forceinline__ unsigned long long fma2(unsigned long long a, unsigned long long b, unsigned long long c) {
    unsigned long long d;
    asm("fma.rn.f32x2 %0, %1, %2, %3;" : "=l"(d) : "l"(a), "l"(b), "l"(c));
    return d;
}

// ---------- bf16 mma helpers (sm_80+ PTX; works on base sm_100) ----------
__device__ __forceinline__ unsigned smem_u32(const void* p) {
    unsigned a;
    asm("{ .reg .u64 t; cvta.to.shared.u64 t, %1; cvt.u32.u64 %0, t; }" : "=r"(a) : "l"(p));
    return a;
}
__device__ __forceinline__ float ex2f(float x) {
    float r;
    asm("ex2.approx.f32 %0, %1;" : "=f"(r) : "f"(x));
    return r;
}
// pack: result.hi = bf16(hi), result.lo = bf16(lo)
__device__ __forceinline__ unsigned bfpack(float hi, float lo) {
    unsigned d;
    asm("cvt.rn.bf16x2.f32 %0, %1, %2;" : "=r"(d) : "f"(hi), "f"(lo));
    return d;
}
// D(16x8,f32) += A(16x16 bf16) * B(16x8 bf16)
__device__ __forceinline__ void mma16(float* c, const unsigned* a, unsigned b0, unsigned b1) {
    asm("mma.sync.aligned.m16n8k16.row.col.f32.bf16.bf16.f32 "
        "{%0,%1,%2,%3}, {%4,%5,%6,%7}, {%8,%9}, {%0,%1,%2,%3};"
        : "+f"(c[0]), "+f"(c[1]), "+f"(c[2]), "+f"(c[3])
        : "r"(a[0]), "r"(a[1]), "r"(a[2]), "r"(a[3]), "r"(b0), "r"(b1));
}
__device__ __forceinline__ void ldm4(unsigned* r, unsigned addr) {
    asm volatile("ldmatrix.sync.aligned.m8n8.x4.shared.b16 {%0,%1,%2,%3}, [%4];"
                 : "=r"(r[0]), "=r"(r[1]), "=r"(r[2]), "=r"(r[3]) : "r"(addr));
}
__device__ __forceinline__ void ldm4t(unsigned* r, unsigned addr) {
    asm volatile("ldmatrix.sync.aligned.m8n8.x4.trans.shared.b16 {%0,%1,%2,%3}, [%4];"
                 : "=r"(r[0]), "=r"(r[1]), "=r"(r[2]), "=r"(r[3]) : "r"(addr));
}
__device__ __forceinline__ void st32(unsigned addr, unsigned v) {
    asm volatile("st.shared.b32 [%0], %1;" :: "r"(addr), "r"(v) : "memory");
}

// =========================================================================
// Projection kernel (unchanged — known good)
// =========================================================================
__global__ __launch_bounds__(256) void proj_kernel(
    const float* __restrict__ x,
    const float* __restrict__ wk1, const float* __restrict__ bk1, const float* __restrict__ wk2,
    const float* __restrict__ wq1, const float* __restrict__ bq1, const float* __restrict__ wq2,
    const float* __restrict__ wv1, const float* __restrict__ bv1, const float* __restrict__ wv2)
{
    __shared__ __align__(16) float smem[12288];
    float* Xs  = smem;
    float* Ws  = smem + 2112;
    float* Hs  = smem;
    float* W2s = smem + 6144;

    const int tid  = threadIdx.x;
    const int tok0 = blockIdx.x * 64;

    {
        for (int idx = tid; idx < 3*32*64; idx += 256) {
            int p = idx >> 11, rem = idx & 2047;
            const float* w2 = (p == 0) ? wk2 : ((p == 1) ? wq2 : wv2);
            W2s[idx] = w2[rem];
        }
    }

    const int tx = tid & 15;
    const int ty = tid >> 4;

    unsigned long long acc2[4][3];
#pragma unroll
    for (int i = 0; i < 4; i++)
#pragma unroll
        for (int j = 0; j < 3; j++) acc2[i][j] = 0ull;

    for (int k0 = 0; k0 < EMB; k0 += 32) {
        __syncthreads();
        for (int idx = tid; idx < 64*32; idx += 256) {
            int t = idx >> 5, kk = idx & 31;
            Xs[t*33 + kk] = x[(long long)(tok0 + t)*EMB + k0 + kk];
        }
        for (int idx = tid; idx < 32*96; idx += 256) {
            int kk = idx / 96, c = idx % 96;
            int p = c >> 5, h = c & 31;
            const float* w1 = (p == 0) ? wk1 : ((p == 1) ? wq1 : wv1);
            Ws[kk*96 + c] = w1[(k0 + kk)*HALF + h];
        }
        __syncthreads();

#pragma unroll
        for (int kk = 0; kk < 32; kk++) {
            unsigned long long a2[4];
#pragma unroll
            for (int i = 0; i < 4; i++) {
                float a = Xs[(ty*4 + i)*33 + kk];
                a2[i] = pk2(a, a);
            }
            unsigned long long b2[3];
#pragma unroll
            for (int j = 0; j < 3; j++)
                b2[j] = *(const unsigned long long*)&Ws[kk*96 + tx*6 + 2*j];
#pragma unroll
            for (int i = 0; i < 4; i++)
#pragma unroll
                for (int j = 0; j < 3; j++)
                    acc2[i][j] = fma2(a2[i], b2[j], acc2[i][j]);
        }
    }
    __syncthreads();

#pragma unroll
    for (int i = 0; i < 4; i++) {
#pragma unroll
        for (int j = 0; j < 3; j++) {
            float lo, hi;
            upk2(acc2[i][j], lo, hi);
            int c0 = tx*6 + 2*j;
            int p0 = c0 >> 5, h0 = c0 & 31;
            const float* b1 = (p0 == 0) ? bk1 : ((p0 == 1) ? bq1 : bv1);
            lo = tanhf(lo + b1[h0]);
            hi = tanhf(hi + b1[h0 + 1]);
            Hs[(ty*4 + i)*96 + c0]     = lo;
            Hs[(ty*4 + i)*96 + c0 + 1] = hi;
        }
    }
    __syncthreads();

    for (int idx = tid; idx < 64*96; idx += 256) {
        int t = idx / 96, cp = idx % 96;
        int p = cp >> 5, hp = cp & 31;
        unsigned long long acc = 0ull;
#pragma unroll
        for (int j = 0; j < 32; j++) {
            float a = Hs[t*96 + p*32 + j];
            unsigned long long b = *(const unsigned long long*)&W2s[p*2048 + j*64 + 2*hp];
            acc = fma2(pk2(a, a), b, acc);
        }
        float lo, hi;
        upk2(acc, lo, hi);
        float* gout = (p == 0) ? g_K : ((p == 1) ? g_Q : g_V);
        long long o = (long long)(tok0 + t)*HD + 2*hp;
        gout[o]     = lo;
        gout[o + 1] = hi;
    }
}

// =========================================================================
// bf16 2-way-split flash attention, m16n8k16 mma + ldmatrix.
//   CTA = 64 queries, 128 threads = 4 warps x 16 query rows; 3 CTAs/SM.
//   K,V staged as hi/lo bf16 planes [64key][64d], 128B rows, unit-swizzled
//   (dblk ^= key&7) -> all ldmatrix phases conflict-free.
//   QK: s = qh*kh + ql*kh + qh*kl (Q frags in regs all kernel).
//   softmax: p = 2^s (log2e folded in Q prescale; no-max, clamp 80).
//   P stays in REGISTERS (QK C-frag == PV A-frag layout); pack hi/lo bf16.
//   PV: o += ph*vh + pl*vh + ph*vl  (V via ldmatrix.trans).
//   Accuracy ~1e-4 (16-17 effective mantissa bits both GEMMs).
// =========================================================================
__global__ __launch_bounds__(128, 3) void attn_bf16(float* __restrict__ out)
{
    __shared__ __align__(1024) unsigned char smb[32768];
    const unsigned sb   = smem_u32(smb);
    const unsigned KHIb = sb;            // [64][64] bf16
    const unsigned KLOb = sb + 8192;
    const unsigned VHIb = sb + 16384;
    const unsigned VLOb = sb + 24576;

    const int tid  = threadIdx.x;
    const int w    = tid >> 5;
    const int lane = tid & 31;
    const int g    = lane >> 2;          // row group 0..7
    const int r    = lane & 3;           // col-in-group 0..3
    const int laneKey = lane & 15;       // ldmatrix row-lane mapping
    const int laneHi  = lane >> 4;
    const int kx      = laneKey & 7;
    const unsigned lmBase = laneKey * 128;

    const int bid = blockIdx.x;
    const int b   = bid & 7;
    const int qt  = 63 - (bid >> 3);     // heavy q-tiles first
    const int nk  = qt + 1;
    const long long qrow0 = (long long)b*SLEN + (long long)qt*64;
    const int q0 = qt*64 + 16*w + g;
    const int q1 = q0 + 8;

    // ---- Q fragments (hi/lo bf16), prescaled by 0.125*log2(e) ----
    const float SC = 0.1803368801111204f;
    unsigned qhi[4][4], qlo[4][4];
    {
        const float* qA = g_Q + (qrow0 + 16*w + g)*HD;
        const float* qB = qA + 8*HD;
#pragma unroll
        for (int c = 0; c < 4; c++) {
#pragma unroll
            for (int u = 0; u < 4; u++) {
                const float* src = (u & 1) ? qB : qA;
                int d = 16*c + 2*r + ((u & 2) ? 8 : 0);
                float2 xv = *(const float2*)(src + d);
                float v0 = xv.x * SC, v1 = xv.y * SC;
                unsigned h = bfpack(v1, v0);
                qhi[c][u] = h;
                float r0 = v0 - __uint_as_float(h << 16);
                float r1 = v1 - __uint_as_float(h & 0xFFFF0000u);
                qlo[c][u] = bfpack(r1, r0);
            }
        }
    }

    float o[8][4];
#pragma unroll
    for (int j = 0; j < 8; j++)
#pragma unroll
        for (int u = 0; u < 4; u++) o[j][u] = 0.f;
    float l0 = 0.f, l1 = 0.f;

    for (int kt = 0; kt < nk; kt++) {
        __syncthreads();   // prior tile's smem reads complete
        // ---- stage K/V as hi/lo bf16, swizzled ----
        {
            const long long kbase = ((long long)b*SLEN + (long long)kt*64) * HD;
            const float2* gk2 = (const float2*)(g_K + kbase);
            const float2* gv2 = (const float2*)(g_V + kbase);
#pragma unroll
            for (int it = 0; it < 16; it++) {
                int idx = tid + it*128;          // 2048 float2 slots
                int key = idx >> 5, pr = idx & 31;
                unsigned off = key*128 + ((((unsigned)(pr >> 2)) ^ (unsigned)(key & 7)) << 4) + (pr & 3)*4;
                float2 kv = gk2[idx];
                unsigned hk = bfpack(kv.y, kv.x);
                st32(KHIb + off, hk);
                float ka = kv.x - __uint_as_float(hk << 16);
                float kb2 = kv.y - __uint_as_float(hk & 0xFFFF0000u);
                st32(KLOb + off, bfpack(kb2, ka));
                float2 vv = gv2[idx];
                unsigned hv = bfpack(vv.y, vv.x);
                st32(VHIb + off, hv);
                float va = vv.x - __uint_as_float(hv << 16);
                float vb = vv.y - __uint_as_float(hv & 0xFFFF0000u);
                st32(VLOb + off, bfpack(vb, va));
            }
        }
        __syncthreads();

        // ---- QK: S[16 x 64] via 3-term bf16 split ----
        float s[8][4];
#pragma unroll
        for (int j = 0; j < 8; j++)
#pragma unroll
            for (int u = 0; u < 4; u++) s[j][u] = 0.f;

#pragma unroll
        for (int c = 0; c < 4; c++) {          // d-chunks of 16
#pragma unroll
            for (int t = 0; t < 4; t++) {      // key pairs-of-groups (16 keys)
                unsigned adr = KHIb + lmBase + t*2048 + ((((unsigned)(2*c + laneHi)) ^ (unsigned)kx) << 4);
                unsigned kh[4], kl[4];
                ldm4(kh, adr);
                ldm4(kl, adr + 8192);
                mma16(s[2*t],   qhi[c], kh[0], kh[2]);
                mma16(s[2*t],   qlo[c], kh[0], kh[2]);
                mma16(s[2*t],   qhi[c], kl[0], kl[2]);
                mma16(s[2*t+1], qhi[c], kh[1], kh[3]);
                mma16(s[2*t+1], qlo[c], kh[1], kh[3]);
                mma16(s[2*t+1], qhi[c], kl[1], kl[3]);
            }
        }

        // ---- softmax (p = 2^s, no-max) + causal mask; p kept in s[][] ----
        const int kb = kt*64;
        if (kt == qt) {       // diagonal tile (uniform branch)
#pragma unroll
            for (int j = 0; j < 8; j++) {
                int k0 = kb + 8*j + 2*r;
                float p0 = (k0     > q0) ? 0.f : ex2f(fminf(s[j][0], 80.f));
                float p1 = (k0 + 1 > q0) ? 0.f : ex2f(fminf(s[j][1], 80.f));
                float p2 = (k0     > q1) ? 0.f : ex2f(fminf(s[j][2], 80.f));
                float p3 = (k0 + 1 > q1) ? 0.f : ex2f(fminf(s[j][3], 80.f));
                l0 += p0 + p1; l1 += p2 + p3;
                s[j][0] = p0; s[j][1] = p1; s[j][2] = p2; s[j][3] = p3;
            }
        } else {
#pragma unroll
            for (int j = 0; j < 8; j++) {
                float p0 = ex2f(fminf(s[j][0], 80.f));
                float p1 = ex2f(fminf(s[j][1], 80.f));
                float p2 = ex2f(fminf(s[j][2], 80.f));
                float p3 = ex2f(fminf(s[j][3], 80.f));
                l0 += p0 + p1; l1 += p2 + p3;
                s[j][0] = p0; s[j][1] = p1; s[j][2] = p2; s[j][3] = p3;
            }
        }

        // ---- pack P into PV A-fragments (registers only; no smem!) ----
        unsigned aph[4][4], apl[4][4];
#pragma unroll
        for (int t = 0; t < 4; t++) {
#pragma unroll
            for (int u = 0; u < 4; u++) {
                // u0: kg 2t rows g   | u1: kg 2t rows g+8
                // u2: kg 2t+1 rows g | u3: kg 2t+1 rows g+8
                int j  = 2*t + ((u & 2) ? 1 : 0);
                int v0 = (u & 1) ? 2 : 0;
                float pa = s[j][v0], pb = s[j][v0 + 1];
                unsigned h = bfpack(pb, pa);
                aph[t][u] = h;
                float ra = pa - __uint_as_float(h << 16);
                float rb = pb - __uint_as_float(h & 0xFFFF0000u);
                apl[t][u] = bfpack(rb, ra);
            }
        }

        // ---- PV: O += P * V via 3-term bf16 split (V through ldmatrix.trans) ----
#pragma unroll
        for (int t = 0; t < 4; t++) {          // key chunks of 16
#pragma unroll
            for (int e = 0; e < 4; e++) {      // d-group pairs (16 dims)
                unsigned adr = VHIb + lmBase + t*2048 + ((((unsigned)(2*e + laneHi)) ^ (unsigned)kx) << 4);
                unsigned vh[4], vl[4];
                ldm4t(vh, adr);
                ldm4t(vl, adr + 8192);
                mma16(o[2*e],   aph[t], vh[0], vh[1]);
                mma16(o[2*e],   apl[t], vh[0], vh[1]);
                mma16(o[2*e],   aph[t], vl[0], vl[1]);
                mma16(o[2*e+1], aph[t], vh[2], vh[3]);
                mma16(o[2*e+1], apl[t], vh[2], vh[3]);
                mma16(o[2*e+1], aph[t], vl[2], vl[3]);
            }
        }
    }

    // ---- reduce l over the 4 lanes of each row; normalize; store ----
    l0 += __shfl_xor_sync(0xffffffffu, l0, 1);
    l0 += __shfl_xor_sync(0xffffffffu, l0, 2);
    l1 += __shfl_xor_sync(0xffffffffu, l1, 1);
    l1 += __shfl_xor_sync(0xffffffffu, l1, 2);
    float inv0 = 1.0f / l0;
    float inv1 = 1.0f / l1;
    float* out0 = out + ((long long)b*SLEN + q0)*HD + 2*r;
    float* out1 = out + ((long long)b*SLEN + q1)*HD + 2*r;
#pragma unroll
    for (int j = 0; j < 8; j++) {
        *(float2*)(out0 + 8*j) = make_float2(o[j][0]*inv0, o[j][1]*inv0);
        *(float2*)(out1 + 8*j) = make_float2(o[j][2]*inv1, o[j][3]*inv1);
    }
}

extern "C" void kernel_launch(void* const* d_in, const int* in_sizes, int n_in,
                              void* d_out, int out_size)
{
    const float* x   = (const float*)d_in[0];
    const float* wk1 = (const float*)d_in[1];
    const float* bk1 = (const float*)d_in[2];
    const float* wk2 = (const float*)d_in[3];
    const float* wq1 = (const float*)d_in[4];
    const float* bq1 = (const float*)d_in[5];
    const float* wq2 = (const float*)d_in[6];
    const float* wv1 = (const float*)d_in[7];
    const float* bv1 = (const float*)d_in[8];
    const float* wv2 = (const float*)d_in[9];

    proj_kernel<<<TOK/64, 256>>>(x, wk1, bk1, wk2, wq1, bq1, wq2, wv1, bv1, wv2);
    attn_bf16<<<NBATCH * (SLEN/64), 128>>>((float*)d_out);
}

// round 10
// speedup vs baseline: 3.1717x; 1.6103x over previous
#include <cuda_runtime.h>

#define SLEN 4096
#define NBATCH 8
#define TOK (NBATCH*SLEN)
#define EMB 1024
#define HD 64
#define HALF 32

// Scratch (device globals: allocation-free rule)
__device__ float g_K[TOK*HD];
__device__ float g_Q[TOK*HD];
__device__ float g_V[TOK*HD];
__device__ unsigned short g_W1h[96*1024];   // W1 transposed [n=p*32+h][k], bf16 hi
__device__ unsigned short g_W1l[96*1024];   // lo residual
__device__ unsigned short g_W2h[192*32];    // W2 transposed [p*64+h][j], bf16 hi
__device__ unsigned short g_W2l[192*32];

// ---------- helpers ----------
__device__ __forceinline__ unsigned smem_u32(const void* p) {
    unsigned a;
    asm("{ .reg .u64 t; cvta.to.shared.u64 t, %1; cvt.u32.u64 %0, t; }" : "=r"(a) : "l"(p));
    return a;
}
__device__ __forceinline__ float ex2f(float x) {
    float r;
    asm("ex2.approx.f32 %0, %1;" : "=f"(r) : "f"(x));
    return r;
}
// pack: result.hi = bf16(hi), result.lo = bf16(lo)
__device__ __forceinline__ unsigned bfpack(float hi, float lo) {
    unsigned d;
    asm("cvt.rn.bf16x2.f32 %0, %1, %2;" : "=r"(d) : "f"(hi), "f"(lo));
    return d;
}
// D(16x8,f32) += A(16x16 bf16) * B(16x8 bf16)
__device__ __forceinline__ void mma16(float* c, const unsigned* a, unsigned b0, unsigned b1) {
    asm("mma.sync.aligned.m16n8k16.row.col.f32.bf16.bf16.f32 "
        "{%0,%1,%2,%3}, {%4,%5,%6,%7}, {%8,%9}, {%0,%1,%2,%3};"
        : "+f"(c[0]), "+f"(c[1]), "+f"(c[2]), "+f"(c[3])
        : "r"(a[0]), "r"(a[1]), "r"(a[2]), "r"(a[3]), "r"(b0), "r"(b1));
}
__device__ __forceinline__ void ldm4(unsigned* r, unsigned addr) {
    asm volatile("ldmatrix.sync.aligned.m8n8.x4.shared.b16 {%0,%1,%2,%3}, [%4];"
                 : "=r"(r[0]), "=r"(r[1]), "=r"(r[2]), "=r"(r[3]) : "r"(addr));
}
__device__ __forceinline__ void ldm4t(unsigned* r, unsigned addr) {
    asm volatile("ldmatrix.sync.aligned.m8n8.x4.trans.shared.b16 {%0,%1,%2,%3}, [%4];"
                 : "=r"(r[0]), "=r"(r[1]), "=r"(r[2]), "=r"(r[3]) : "r"(addr));
}
__device__ __forceinline__ void st32(unsigned addr, unsigned v) {
    asm volatile("st.shared.b32 [%0], %1;" :: "r"(addr), "r"(v) : "memory");
}

// =========================================================================
// conv_w: one-time weight transpose + bf16 hi/lo split (L2-resident data).
// =========================================================================
__global__ void conv_w(
    const float* __restrict__ wk1, const float* __restrict__ wq1, const float* __restrict__ wv1,
    const float* __restrict__ wk2, const float* __restrict__ wq2, const float* __restrict__ wv2)
{
    int i = blockIdx.x*blockDim.x + threadIdx.x;
    int stride = gridDim.x*blockDim.x;
    for (int idx = i; idx < 96*1024; idx += stride) {
        int n = idx >> 10, k = idx & 1023;
        int p = n >> 5, h = n & 31;
        const float* w1 = (p == 0) ? wk1 : ((p == 1) ? wq1 : wv1);
        float v = w1[k*HALF + h];
        unsigned hb = bfpack(0.f, v) & 0xFFFFu;
        float res = v - __uint_as_float(hb << 16);
        g_W1h[idx] = (unsigned short)hb;
        g_W1l[idx] = (unsigned short)(bfpack(0.f, res) & 0xFFFFu);
    }
    for (int idx = i; idx < 192*32; idx += stride) {
        int row = idx >> 5, j = idx & 31;
        int p = row >> 6, h = row & 63;
        const float* w2 = (p == 0) ? wk2 : ((p == 1) ? wq2 : wv2);
        float v = w2[j*HD + h];
        unsigned hb = bfpack(0.f, v) & 0xFFFFu;
        float res = v - __uint_as_float(hb << 16);
        g_W2h[idx] = (unsigned short)hb;
        g_W2l[idx] = (unsigned short)(bfpack(0.f, res) & 0xFFFFu);
    }
}

// =========================================================================
// proj_mma: H = tanh(X W1 + b1); {K,Q,V} = H W2 — all on tensor cores.
//   Block = 64 tokens, 128 threads = 4 warps x 16 token rows.
//   GEMM1: per 64-k slab, X staged hi/lo bf16 (split in-kernel), W1t staged
//   from preconverted planes; 3-term split mma. C-frags (12 n-tiles) get
//   bias+tanh in regs, re-split to bf16, and feed GEMM2 A-frags DIRECTLY
//   (C-frag layout == A-frag layout). GEMM2 B = W2t (pitch 80B, ldmatrix).
//   Outputs stored straight to g_K/g_Q/g_V.
// =========================================================================
#define PSM_XH 0
#define PSM_XL 8192
#define PSM_W1H 16384
#define PSM_W1L 28672
#define PSM_W2H 40960
#define PSM_W2L 56320
#define PSM_BYTES 71680

__global__ __launch_bounds__(128, 2) void proj_mma(
    const float* __restrict__ x,
    const float* __restrict__ bk1, const float* __restrict__ bq1, const float* __restrict__ bv1)
{
    extern __shared__ __align__(1024) unsigned char dsm[];
    const unsigned sb = smem_u32(dsm);
    const unsigned XHa = sb + PSM_XH,  XLa = sb + PSM_XL;
    const unsigned W1Ha = sb + PSM_W1H;
    const unsigned W2Ha = sb + PSM_W2H;

    const int tid = threadIdx.x;
    const int w    = tid >> 5;
    const int lane = tid & 31;
    const int g = lane >> 2, r = lane & 3;
    const int laneKey = lane & 15, laneHi = lane >> 4;
    const int tok0 = blockIdx.x * 64;

    // ---- stage W2t once (pitch 80B rows; 80 % 16 == 0) ----
#pragma unroll
    for (int it = 0; it < 6; it++) {
        int idx = tid + it*128;              // 768 uint4 per plane
        int row = idx >> 2, f = idx & 3;
        *(uint4*)(dsm + PSM_W2H + row*80 + f*16) = *(const uint4*)(g_W2h + row*32 + 8*f);
        *(uint4*)(dsm + PSM_W2L + row*80 + f*16) = *(const uint4*)(g_W2l + row*32 + 8*f);
    }

    float Cf[12][4];
#pragma unroll
    for (int nt = 0; nt < 12; nt++)
#pragma unroll
        for (int u = 0; u < 4; u++) Cf[nt][u] = 0.f;

    for (int s = 0; s < 16; s++) {           // 64-k slabs
        __syncthreads();                     // prior slab reads done (also covers W2t staging)
        // ---- stage X slab (split to hi/lo bf16, swizzled 128B rows) ----
        {
            const float4* gx = (const float4*)x;
#pragma unroll
            for (int it = 0; it < 8; it++) {
                int idx = tid + it*128;      // 1024 float4
                int row = idx >> 4, f = idx & 15;
                float4 v = gx[(long long)(tok0 + row)*256 + s*16 + f];
                unsigned h0 = bfpack(v.y, v.x);
                float r0 = v.x - __uint_as_float(h0 << 16);
                float r1 = v.y - __uint_as_float(h0 & 0xFFFF0000u);
                unsigned l0 = bfpack(r1, r0);
                unsigned h1 = bfpack(v.w, v.z);
                float r2 = v.z - __uint_as_float(h1 << 16);
                float r3 = v.w - __uint_as_float(h1 & 0xFFFF0000u);
                unsigned l1 = bfpack(r3, r2);
                unsigned off = row*128 + ((((unsigned)(f >> 1)) ^ (unsigned)(row & 7)) << 4) + (f & 1)*8;
                st32(XHa + off, h0); st32(XHa + off + 4, h1);
                st32(XLa + off, l0); st32(XLa + off + 4, l1);
            }
        }
        // ---- stage W1t slab (already bf16 hi/lo in gmem) ----
#pragma unroll
        for (int it = 0; it < 6; it++) {
            int idx = tid + it*128;          // 768 uint4 per plane
            int row = idx >> 3, f = idx & 7;
            unsigned off = row*128 + (((unsigned)f ^ (unsigned)(row & 7)) << 4);
            *(uint4*)(dsm + PSM_W1H + off) = *(const uint4*)(g_W1h + row*1024 + s*64 + 8*f);
            *(uint4*)(dsm + PSM_W1L + off) = *(const uint4*)(g_W1l + row*1024 + s*64 + 8*f);
        }
        __syncthreads();

        // ---- GEMM1: Cf += X * W1t (3-term bf16 split) ----
#pragma unroll
        for (int c = 0; c < 4; c++) {        // 16-k chunks
            unsigned axh[4], axl[4];
            unsigned adrA = XHa + (16*w + laneKey)*128
                          + ((((unsigned)(2*c + laneHi)) ^ (unsigned)(laneKey & 7)) << 4);
            ldm4(axh, adrA);
            ldm4(axl, adrA + (PSM_XL - PSM_XH));
#pragma unroll
            for (int tp = 0; tp < 6; tp++) { // n-tile pairs (16 cols)
                unsigned adrB = W1Ha + (16*tp + laneKey)*128
                              + ((((unsigned)(2*c + laneHi)) ^ (unsigned)(laneKey & 7)) << 4);
                unsigned bh[4], bl[4];
                ldm4(bh, adrB);
                ldm4(bl, adrB + (PSM_W1L - PSM_W1H));
                mma16(Cf[2*tp],   axh, bh[0], bh[2]);
                mma16(Cf[2*tp],   axl, bh[0], bh[2]);
                mma16(Cf[2*tp],   axh, bl[0], bl[2]);
                mma16(Cf[2*tp+1], axh, bh[1], bh[3]);
                mma16(Cf[2*tp+1], axl, bh[1], bh[3]);
                mma16(Cf[2*tp+1], axh, bl[1], bl[3]);
            }
        }
    }

    // ---- bias + tanh in registers ----
#pragma unroll
    for (int nt = 0; nt < 12; nt++) {
        int p = nt >> 2;
        int h0 = (nt & 3)*8 + 2*r;
        const float* b1 = (p == 0) ? bk1 : ((p == 1) ? bq1 : bv1);
        float bb0 = b1[h0], bb1 = b1[h0 + 1];
        Cf[nt][0] = tanhf(Cf[nt][0] + bb0);
        Cf[nt][1] = tanhf(Cf[nt][1] + bb1);
        Cf[nt][2] = tanhf(Cf[nt][2] + bb0);
        Cf[nt][3] = tanhf(Cf[nt][3] + bb1);
    }

    // ---- GEMM2: {K,Q,V}[64 tok][64 h] = H_p * W2t_p (H from registers) ----
#pragma unroll
    for (int p = 0; p < 3; p++) {
        float o2[8][4];
#pragma unroll
        for (int e = 0; e < 8; e++)
#pragma unroll
            for (int u = 0; u < 4; u++) o2[e][u] = 0.f;

#pragma unroll
        for (int kc = 0; kc < 2; kc++) {     // 16-j chunks
            int nt0 = 4*p + 2*kc;
            unsigned ah[4], al[4];
#pragma unroll
            for (int u = 0; u < 4; u++) {
                int nt = nt0 + ((u & 2) ? 1 : 0);
                int v0 = (u & 1) ? 2 : 0;
                float pa = Cf[nt][v0], pb = Cf[nt][v0 + 1];
                unsigned hh = bfpack(pb, pa);
                ah[u] = hh;
                float ra = pa - __uint_as_float(hh << 16);
                float rb = pb - __uint_as_float(hh & 0xFFFF0000u);
                al[u] = bfpack(rb, ra);
            }
#pragma unroll
            for (int e2 = 0; e2 < 4; e2++) {
                unsigned adr = W2Ha + (p*64 + 16*e2 + laneKey)*80 + kc*32 + laneHi*16;
                unsigned bh[4], bl[4];
                ldm4(bh, adr);
                ldm4(bl, adr + (PSM_W2L - PSM_W2H));
                mma16(o2[2*e2],   ah, bh[0], bh[2]);
                mma16(o2[2*e2],   al, bh[0], bh[2]);
                mma16(o2[2*e2],   ah, bl[0], bl[2]);
                mma16(o2[2*e2+1], ah, bh[1], bh[3]);
                mma16(o2[2*e2+1], al, bh[1], bh[3]);
                mma16(o2[2*e2+1], ah, bl[1], bl[3]);
            }
        }

        float* gout = (p == 0) ? g_K : ((p == 1) ? g_Q : g_V);
        long long row0 = tok0 + 16*w + g;
#pragma unroll
        for (int e = 0; e < 8; e++) {
            int h0 = 8*e + 2*r;
            *(float2*)&gout[row0*HD + h0]       = make_float2(o2[e][0], o2[e][1]);
            *(float2*)&gout[(row0 + 8)*HD + h0] = make_float2(o2[e][2], o2[e][3]);
        }
    }
}

// =========================================================================
// bf16 2-way-split flash attention (unchanged from R9 — 229us, rel_err 6e-6)
// =========================================================================
__global__ __launch_bounds__(128, 3) void attn_bf16(float* __restrict__ out)
{
    __shared__ __align__(1024) unsigned char smb[32768];
    const unsigned sb   = smem_u32(smb);
    const unsigned KHIb = sb;
    const unsigned KLOb = sb + 8192;
    const unsigned VHIb = sb + 16384;
    const unsigned VLOb = sb + 24576;

    const int tid  = threadIdx.x;
    const int w    = tid >> 5;
    const int lane = tid & 31;
    const int g    = lane >> 2;
    const int r    = lane & 3;
    const int laneKey = lane & 15;
    const int laneHi  = lane >> 4;
    const int kx      = laneKey & 7;
    const unsigned lmBase = laneKey * 128;

    const int bid = blockIdx.x;
    const int b   = bid & 7;
    const int qt  = 63 - (bid >> 3);
    const int nk  = qt + 1;
    const long long qrow0 = (long long)b*SLEN + (long long)qt*64;
    const int q0 = qt*64 + 16*w + g;
    const int q1 = q0 + 8;

    const float SC = 0.1803368801111204f;    // 1/sqrt(64) * log2(e)
    unsigned qhi[4][4], qlo[4][4];
    {
        const float* qA = g_Q + (qrow0 + 16*w + g)*HD;
        const float* qB = qA + 8*HD;
#pragma unroll
        for (int c = 0; c < 4; c++) {
#pragma unroll
            for (int u = 0; u < 4; u++) {
                const float* src = (u & 1) ? qB : qA;
                int d = 16*c + 2*r + ((u & 2) ? 8 : 0);
                float2 xv = *(const float2*)(src + d);
                float v0 = xv.x * SC, v1 = xv.y * SC;
                unsigned h = bfpack(v1, v0);
                qhi[c][u] = h;
                float r0 = v0 - __uint_as_float(h << 16);
                float r1 = v1 - __uint_as_float(h & 0xFFFF0000u);
                qlo[c][u] = bfpack(r1, r0);
            }
        }
    }

    float o[8][4];
#pragma unroll
    for (int j = 0; j < 8; j++)
#pragma unroll
        for (int u = 0; u < 4; u++) o[j][u] = 0.f;
    float l0 = 0.f, l1 = 0.f;

    for (int kt = 0; kt < nk; kt++) {
        __syncthreads();
        {
            const long long kbase = ((long long)b*SLEN + (long long)kt*64) * HD;
            const float2* gk2 = (const float2*)(g_K + kbase);
            const float2* gv2 = (const float2*)(g_V + kbase);
#pragma unroll
            for (int it = 0; it < 16; it++) {
                int idx = tid + it*128;
                int key = idx >> 5, pr = idx & 31;
                unsigned off = key*128 + ((((unsigned)(pr >> 2)) ^ (unsigned)(key & 7)) << 4) + (pr & 3)*4;
                float2 kv = gk2[idx];
                unsigned hk = bfpack(kv.y, kv.x);
                st32(KHIb + off, hk);
                float ka = kv.x - __uint_as_float(hk << 16);
                float kb2 = kv.y - __uint_as_float(hk & 0xFFFF0000u);
                st32(KLOb + off, bfpack(kb2, ka));
                float2 vv = gv2[idx];
                unsigned hv = bfpack(vv.y, vv.x);
                st32(VHIb + off, hv);
                float va = vv.x - __uint_as_float(hv << 16);
                float vb = vv.y - __uint_as_float(hv & 0xFFFF0000u);
                st32(VLOb + off, bfpack(vb, va));
            }
        }
        __syncthreads();

        float s[8][4];
#pragma unroll
        for (int j = 0; j < 8; j++)
#pragma unroll
            for (int u = 0; u < 4; u++) s[j][u] = 0.f;

#pragma unroll
        for (int c = 0; c < 4; c++) {
#pragma unroll
            for (int t = 0; t < 4; t++) {
                unsigned adr = KHIb + lmBase + t*2048 + ((((unsigned)(2*c + laneHi)) ^ (unsigned)kx) << 4);
                unsigned kh[4], kl[4];
                ldm4(kh, adr);
                ldm4(kl, adr + 8192);
                mma16(s[2*t],   qhi[c], kh[0], kh[2]);
                mma16(s[2*t],   qlo[c], kh[0], kh[2]);
                mma16(s[2*t],   qhi[c], kl[0], kl[2]);
                mma16(s[2*t+1], qhi[c], kh[1], kh[3]);
                mma16(s[2*t+1], qlo[c], kh[1], kh[3]);
                mma16(s[2*t+1], qhi[c], kl[1], kl[3]);
            }
        }

        const int kb = kt*64;
        if (kt == qt) {
#pragma unroll
            for (int j = 0; j < 8; j++) {
                int k0 = kb + 8*j + 2*r;
                float p0 = (k0     > q0) ? 0.f : ex2f(fminf(s[j][0], 80.f));
                float p1 = (k0 + 1 > q0) ? 0.f : ex2f(fminf(s[j][1], 80.f));
                float p2 = (k0     > q1) ? 0.f : ex2f(fminf(s[j][2], 80.f));
                float p3 = (k0 + 1 > q1) ? 0.f : ex2f(fminf(s[j][3], 80.f));
                l0 += p0 + p1; l1 += p2 + p3;
                s[j][0] = p0; s[j][1] = p1; s[j][2] = p2; s[j][3] = p3;
            }
        } else {
#pragma unroll
            for (int j = 0; j < 8; j++) {
                float p0 = ex2f(fminf(s[j][0], 80.f));
                float p1 = ex2f(fminf(s[j][1], 80.f));
                float p2 = ex2f(fminf(s[j][2], 80.f));
                float p3 = ex2f(fminf(s[j][3], 80.f));
                l0 += p0 + p1; l1 += p2 + p3;
                s[j][0] = p0; s[j][1] = p1; s[j][2] = p2; s[j][3] = p3;
            }
        }

        unsigned aph[4][4], apl[4][4];
#pragma unroll
        for (int t = 0; t < 4; t++) {
#pragma unroll
            for (int u = 0; u < 4; u++) {
                int j  = 2*t + ((u & 2) ? 1 : 0);
                int v0 = (u & 1) ? 2 : 0;
                float pa = s[j][v0], pb = s[j][v0 + 1];
                unsigned h = bfpack(pb, pa);
                aph[t][u] = h;
                float ra = pa - __uint_as_float(h << 16);
                float rb = pb - __uint_as_float(h & 0xFFFF0000u);
                apl[t][u] = bfpack(rb, ra);
            }
        }

#pragma unroll
        for (int t = 0; t < 4; t++) {
#pragma unroll
            for (int e = 0; e < 4; e++) {
                unsigned adr = VHIb + lmBase + t*2048 + ((((unsigned)(2*e + laneHi)) ^ (unsigned)kx) << 4);
                unsigned vh[4], vl[4];
                ldm4t(vh, adr);
                ldm4t(vl, adr + 8192);
                mma16(o[2*e],   aph[t], vh[0], vh[1]);
                mma16(o[2*e],   apl[t], vh[0], vh[1]);
                mma16(o[2*e],   aph[t], vl[0], vl[1]);
                mma16(o[2*e+1], aph[t], vh[2], vh[3]);
                mma16(o[2*e+1], apl[t], vh[2], vh[3]);
                mma16(o[2*e+1], aph[t], vl[2], vl[3]);
            }
        }
    }

    l0 += __shfl_xor_sync(0xffffffffu, l0, 1);
    l0 += __shfl_xor_sync(0xffffffffu, l0, 2);
    l1 += __shfl_xor_sync(0xffffffffu, l1, 1);
    l1 += __shfl_xor_sync(0xffffffffu, l1, 2);
    float inv0 = 1.0f / l0;
    float inv1 = 1.0f / l1;
    float* out0 = out + ((long long)b*SLEN + q0)*HD + 2*r;
    float* out1 = out + ((long long)b*SLEN + q1)*HD + 2*r;
#pragma unroll
    for (int j = 0; j < 8; j++) {
        *(float2*)(out0 + 8*j) = make_float2(o[j][0]*inv0, o[j][1]*inv0);
        *(float2*)(out1 + 8*j) = make_float2(o[j][2]*inv1, o[j][3]*inv1);
    }
}

extern "C" void kernel_launch(void* const* d_in, const int* in_sizes, int n_in,
                              void* d_out, int out_size)
{
    const float* x   = (const float*)d_in[0];
    const float* wk1 = (const float*)d_in[1];
    const float* bk1 = (const float*)d_in[2];
    const float* wk2 = (const float*)d_in[3];
    const float* wq1 = (const float*)d_in[4];
    const float* bq1 = (const float*)d_in[5];
    const float* wq2 = (const float*)d_in[6];
    const float* wv1 = (const float*)d_in[7];
    const float* bv1 = (const float*)d_in[8];
    const float* wv2 = (const float*)d_in[9];

    cudaFuncSetAttribute(proj_mma, cudaFuncAttributeMaxDynamicSharedMemorySize, PSM_BYTES);

    conv_w<<<96, 256>>>(wk1, wq1, wv1, wk2, wq2, wv2);
    proj_mma<<<TOK/64, 128, PSM_BYTES>>>(x, bk1, bq1, bv1);
    attn_bf16<<<NBATCH * (SLEN/64), 128>>>((float*)d_out);
}